// round 5
// baseline (speedup 1.0000x reference)
#include <cuda_runtime.h>
#include <cuda_fp16.h>

#define BB 4
#define TT 32
#define NN 32
#define FF 16
#define GH 64
#define LSTM_IN 2048
#define LSTM_H 4096
#define G4 16384
#define EE 256

typedef unsigned long long u64t;

// Static scratch (no runtime allocation allowed)
__device__ float d_A[NN * NN];
__device__ float d_seq[BB * TT * LSTM_IN];        // GCN output, 1 MB
__device__ float d_XP[BB * TT * G4];              // x_proj, 8 MB
__device__ float d_H[2][BB * LSTM_H];             // hidden ping-pong
__device__ float d_C[BB * LSTM_H];                // cell state
__device__ __half d_Whh[(size_t)G4 * LSTM_H];     // fp16 W_hh, 134 MB
__device__ __half d_Wih[(size_t)G4 * LSTM_IN];    // fp16 W_ih, 67 MB

// ---- f32x2 packed-FMA helpers (full fp32 precision, 2x FFMA rate) ----------
__device__ __forceinline__ void fma2(u64t& d, u64t a, u64t b) {
    asm("fma.rn.f32x2 %0, %1, %2, %0;" : "+l"(d) : "l"(a), "l"(b));
}
__device__ __forceinline__ float2 upk(u64t v) {
    float2 f; asm("mov.b64 {%0, %1}, %2;" : "=f"(f.x), "=f"(f.y) : "l"(v)); return f;
}
// half2 -> packed f32x2
__device__ __forceinline__ u64t h2f2(unsigned h2) {
    u64t r;
    asm("{.reg .f16 lo, hi;\n\t"
        " .reg .f32 flo, fhi;\n\t"
        " mov.b32 {lo, hi}, %1;\n\t"
        " cvt.f32.f16 flo, lo;\n\t"
        " cvt.f32.f16 fhi, hi;\n\t"
        " mov.b64 %0, {flo, fhi};}"
        : "=l"(r) : "r"(h2));
    return r;
}

// ---------------------------------------------------------------------------
// fp32 -> fp16 conversion, 8 elements/thread
// ---------------------------------------------------------------------------
__global__ void k_cvt(const float* __restrict__ src, __half* __restrict__ dst, int n8) {
    int i = blockIdx.x * blockDim.x + threadIdx.x;
    if (i >= n8) return;
    const float4* s4 = (const float4*)src;
    float4 a = s4[(size_t)i * 2], b = s4[(size_t)i * 2 + 1];
    union { __half2 h[4]; uint4 u; } o;
    o.h[0] = __floats2half2_rn(a.x, a.y);
    o.h[1] = __floats2half2_rn(a.z, a.w);
    o.h[2] = __floats2half2_rn(b.x, b.y);
    o.h[3] = __floats2half2_rn(b.z, b.w);
    ((uint4*)dst)[i] = o.u;
}

// ---------------------------------------------------------------------------
// Dense adjacency (sym-norm + self loops); zero h/c. Runtime int32/64 sniff.
// ---------------------------------------------------------------------------
__global__ void k_setup(const long long* __restrict__ e64,
                        const int* __restrict__ e32) {
    __shared__ float sdeg[NN];
    __shared__ float sdinv[NN];
    __shared__ float sA[NN * NN];
    __shared__ int s_is64;
    int tid = threadIdx.x;

    if (tid == 0) s_is64 = 1;
    if (tid < NN) sdeg[tid] = 1.0f;
    for (int i = tid; i < NN * NN; i += blockDim.x) sA[i] = 0.f;
    __syncthreads();
    {
        long long v = e64[tid];
        if (v < 0 || v >= NN) atomicExch(&s_is64, 0);
    }
    __syncthreads();
    int is64 = s_is64;
    {
        int d = is64 ? (int)e64[EE + tid] : e32[EE + tid];
        if (d >= 0 && d < NN) atomicAdd(&sdeg[d], 1.0f);
    }
    __syncthreads();
    if (tid < NN) sdinv[tid] = rsqrtf(sdeg[tid]);
    __syncthreads();
    {
        int s = is64 ? (int)e64[tid]      : e32[tid];
        int d = is64 ? (int)e64[EE + tid] : e32[EE + tid];
        if (s >= 0 && s < NN && d >= 0 && d < NN)
            atomicAdd(&sA[d * NN + s], sdinv[s] * sdinv[d]);
    }
    __syncthreads();
    if (tid < NN) atomicAdd(&sA[tid * NN + tid], sdinv[tid] * sdinv[tid]);
    __syncthreads();
    for (int i = tid; i < NN * NN; i += blockDim.x) d_A[i] = sA[i];
    float* h = &d_H[0][0];
    for (int i = tid; i < 2 * BB * LSTM_H; i += blockDim.x) h[i] = 0.f;
    for (int i = tid; i < BB * LSTM_H; i += blockDim.x) d_C[i] = 0.f;
}

// ---------------------------------------------------------------------------
// Fused LayerNorm + GCN1 + GCN2 per (b,t) slice.
// ---------------------------------------------------------------------------
__global__ void k_gcn(const float* __restrict__ x,
                      const float* __restrict__ ln_g, const float* __restrict__ ln_b,
                      const float* __restrict__ W1, const float* __restrict__ b1,
                      const float* __restrict__ W2, const float* __restrict__ b2) {
    __shared__ float sA[NN * NN];
    __shared__ float sW1[FF * GH];
    __shared__ float sW2[GH * GH];
    __shared__ float sx[NN][FF];
    __shared__ float sb1[NN][GH];
    __shared__ float sb2[NN][GH];
    int tid = threadIdx.x;
    int bt = blockIdx.x;
    const float* xb = x + bt * NN * FF;

    for (int i = tid; i < NN * NN; i += 256) sA[i] = d_A[i];
    for (int i = tid; i < FF * GH; i += 256) sW1[i] = W1[i];
    for (int i = tid; i < GH * GH; i += 256) sW2[i] = W2[i];
    if (tid < NN) {
        float mu = 0.f;
        #pragma unroll
        for (int f = 0; f < FF; f++) mu += xb[tid * FF + f];
        mu *= (1.0f / FF);
        float var = 0.f;
        #pragma unroll
        for (int f = 0; f < FF; f++) { float d = xb[tid * FF + f] - mu; var += d * d; }
        var *= (1.0f / FF);
        float rs = rsqrtf(var + 1e-5f);
        #pragma unroll
        for (int f = 0; f < FF; f++)
            sx[tid][f] = (xb[tid * FF + f] - mu) * rs * ln_g[f] + ln_b[f];
    }
    __syncthreads();
    for (int i = tid; i < NN * GH; i += 256) {
        int n = i >> 6, g = i & 63;
        float s = 0.f;
        #pragma unroll
        for (int f = 0; f < FF; f++) s += sx[n][f] * sW1[f * GH + g];
        sb1[n][g] = s;
    }
    __syncthreads();
    for (int i = tid; i < NN * GH; i += 256) {
        int n = i >> 6, g = i & 63;
        float s = b1[g];
        #pragma unroll
        for (int m = 0; m < NN; m++) s += sA[n * NN + m] * sb1[m][g];
        sb2[n][g] = s;
    }
    __syncthreads();
    for (int i = tid; i < NN * GH; i += 256) {
        int n = i >> 6, g = i & 63;
        float s = 0.f;
        #pragma unroll
        for (int k = 0; k < GH; k++) s += sb2[n][k] * sW2[k * GH + g];
        sb1[n][g] = s;
    }
    __syncthreads();
    for (int i = tid; i < NN * GH; i += 256) {
        int n = i >> 6, g = i & 63;
        float s = b2[g];
        #pragma unroll
        for (int m = 0; m < NN; m++) s += sA[n * NN + m] * sb1[m][g];
        d_seq[bt * LSTM_IN + i] = s;
    }
}

// ---------------------------------------------------------------------------
// x_proj: warp = 2 rows x 16 bt, fp16 W_ih, f32x2 packed FMA; seq loaded as
// packed u64 pairs. grid (1024, 8) x 256 threads.
// ---------------------------------------------------------------------------
__global__ void __launch_bounds__(256) k_xproj(const float* __restrict__ bih,
                                               const float* __restrict__ bhh) {
    int lane = threadIdx.x & 31;
    int w = threadIdx.x >> 5;
    int row = blockIdx.x * 16 + w * 2;   // rows row, row+1
    int bt0 = blockIdx.y * 16;

    u64t acc[2][16];
    #pragma unroll
    for (int r = 0; r < 2; r++)
        #pragma unroll
        for (int j = 0; j < 16; j++) acc[r][j] = 0ull;

    const uint4* W0 = (const uint4*)(d_Wih + (size_t)row * LSTM_IN);
    const uint4* W1 = (const uint4*)(d_Wih + (size_t)(row + 1) * LSTM_IN);

    #pragma unroll 2
    for (int kc = 0; kc < 8; kc++) {
        int g = kc * 32 + lane;          // granule of 8 k
        uint4 wa = W0[g], wb = W1[g];
        u64t wA0 = h2f2(wa.x), wA1 = h2f2(wa.y), wA2 = h2f2(wa.z), wA3 = h2f2(wa.w);
        u64t wB0 = h2f2(wb.x), wB1 = h2f2(wb.y), wB2 = h2f2(wb.z), wB3 = h2f2(wb.w);
        #pragma unroll
        for (int j = 0; j < 16; j++) {
            const ulonglong2* S = (const ulonglong2*)(d_seq + (size_t)(bt0 + j) * LSTM_IN);
            ulonglong2 s0 = S[g * 2], s1 = S[g * 2 + 1];
            fma2(acc[0][j], wA0, s0.x); fma2(acc[0][j], wA1, s0.y);
            fma2(acc[0][j], wA2, s1.x); fma2(acc[0][j], wA3, s1.y);
            fma2(acc[1][j], wB0, s0.x); fma2(acc[1][j], wB1, s0.y);
            fma2(acc[1][j], wB2, s1.x); fma2(acc[1][j], wB3, s1.y);
        }
    }
    #pragma unroll
    for (int r = 0; r < 2; r++) {
        #pragma unroll
        for (int j = 0; j < 16; j++) {
            float2 f = upk(acc[r][j]);
            float v = f.x + f.y;
            #pragma unroll
            for (int o = 16; o; o >>= 1) v += __shfl_xor_sync(0xffffffffu, v, o);
            if (lane == 0) {
                int rr = row + r;
                d_XP[(size_t)(bt0 + j) * G4 + rr] = v + bih[rr] + bhh[rr];
            }
        }
    }
}

// ---------------------------------------------------------------------------
// One LSTM step, fp16 W_hh. 256 threads (8 warps = 8 units), grid 512.
// h staged in smem (LDS path); W double-buffered (guaranteed MLP).
// launch_bounds(256,3): 24 warps/SM, 85-reg budget (R3 used 76).
// ---------------------------------------------------------------------------
__global__ void __launch_bounds__(256, 3) k_step(int t) {
    __shared__ float sh[BB * LSTM_H];    // 64 KB
    int tid = threadIdx.x;
    const float* hin = d_H[t & 1];
    float* hout = d_H[(t + 1) & 1];

    // stage h: 16384 floats = 256 threads x 16 float4
    {
        const float4* h4 = (const float4*)hin;
        float4* s4 = (float4*)sh;
        #pragma unroll
        for (int i = 0; i < 16; i++)
            s4[tid + i * 256] = h4[tid + i * 256];
    }
    __syncthreads();

    int gw = blockIdx.x * 8 + (tid >> 5);    // unit 0..4095
    int lane = tid & 31;

    const uint4* Wp[4];
    #pragma unroll
    for (int r = 0; r < 4; r++)
        Wp[r] = (const uint4*)(d_Whh + (size_t)(gw + r * LSTM_H) * LSTM_H);

    u64t acc[4][4];
    #pragma unroll
    for (int r = 0; r < 4; r++)
        #pragma unroll
        for (int b = 0; b < 4; b++) acc[r][b] = 0ull;

    uint4 wbuf[4];
    #pragma unroll
    for (int r = 0; r < 4; r++) wbuf[r] = Wp[r][lane];

    const ulonglong2* sh2 = (const ulonglong2*)sh;

    #pragma unroll 1
    for (int kc = 0; kc < 16; kc++) {
        int g = kc * 32 + lane;
        ulonglong2 hv0[4], hv1[4];
        #pragma unroll
        for (int b = 0; b < 4; b++) {
            hv0[b] = sh2[b * 1024 + g * 2];
            hv1[b] = sh2[b * 1024 + g * 2 + 1];
        }
        #pragma unroll
        for (int r = 0; r < 4; r++) {
            uint4 wu = wbuf[r];
            if (kc < 15) wbuf[r] = Wp[r][g + 32];   // prefetch next granule
            u64t w0 = h2f2(wu.x), w1 = h2f2(wu.y), w2 = h2f2(wu.z), w3 = h2f2(wu.w);
            #pragma unroll
            for (int b = 0; b < 4; b++) {
                fma2(acc[r][b], w0, hv0[b].x);
                fma2(acc[r][b], w1, hv0[b].y);
                fma2(acc[r][b], w2, hv1[b].x);
                fma2(acc[r][b], w3, hv1[b].y);
            }
        }
    }

    float fa[4][4];
    #pragma unroll
    for (int r = 0; r < 4; r++)
        #pragma unroll
        for (int b = 0; b < 4; b++) {
            float2 f = upk(acc[r][b]);
            float v = f.x + f.y;
            #pragma unroll
            for (int o = 16; o; o >>= 1) v += __shfl_xor_sync(0xffffffffu, v, o);
            fa[r][b] = v;
        }

    if (lane == 0) {
        #pragma unroll
        for (int b = 0; b < 4; b++) {
            size_t xb = ((size_t)b * TT + t) * G4;
            float gi = fa[0][b] + d_XP[xb + gw];
            float gf = fa[1][b] + d_XP[xb + gw + 4096];
            float gg = fa[2][b] + d_XP[xb + gw + 8192];
            float go = fa[3][b] + d_XP[xb + gw + 12288];
            float si = 1.f / (1.f + expf(-gi));
            float sf = 1.f / (1.f + expf(-gf));
            float so = 1.f / (1.f + expf(-go));
            float c = sf * d_C[b * LSTM_H + gw] + si * tanhf(gg);
            d_C[b * LSTM_H + gw] = c;
            hout[b * LSTM_H + gw] = so * tanhf(c);
        }
    }
}

// ---------------------------------------------------------------------------
// Final FC
// ---------------------------------------------------------------------------
__global__ void k_fc(const float* __restrict__ fcW, const float* __restrict__ fcb,
                     float* __restrict__ out) {
    int i = threadIdx.x;  // 0..127
    int b = i >> 5, n = i & 31;
    const float* h = &d_H[0][0] + b * LSTM_H + n * 128;  // T=32 -> parity 0
    float s = 0.f;
    #pragma unroll
    for (int l = 0; l < 128; l++) s += h[l] * fcW[l];
    out[i] = s + fcb[0];
}

extern "C" void kernel_launch(void* const* d_in, const int* in_sizes, int n_in,
                              void* d_out, int out_size) {
    const float* x       = (const float*)d_in[0];
    const void*  ei      = d_in[1];
    const float* ln_g    = (const float*)d_in[2];
    const float* ln_b    = (const float*)d_in[3];
    const float* W1      = (const float*)d_in[4];
    const float* b1      = (const float*)d_in[5];
    const float* W2      = (const float*)d_in[6];
    const float* b2      = (const float*)d_in[7];
    const float* Wih     = (const float*)d_in[8];
    const float* bih     = (const float*)d_in[9];
    const float* Whh     = (const float*)d_in[10];
    const float* bhh     = (const float*)d_in[11];
    const float* fcW     = (const float*)d_in[12];
    const float* fcb     = (const float*)d_in[13];

    __half* whh_h = nullptr;  cudaGetSymbolAddress((void**)&whh_h, d_Whh);
    __half* wih_h = nullptr;  cudaGetSymbolAddress((void**)&wih_h, d_Wih);

    k_setup<<<1, 256>>>((const long long*)ei, (const int*)ei);
    k_cvt<<<(G4 * LSTM_H / 8 + 255) / 256, 256>>>(Whh, whh_h, G4 * LSTM_H / 8);
    k_cvt<<<(G4 * LSTM_IN / 8 + 255) / 256, 256>>>(Wih, wih_h, G4 * LSTM_IN / 8);
    k_gcn<<<BB * TT, 256>>>(x, ln_g, ln_b, W1, b1, W2, b2);
    dim3 gx(G4 / 16, 8);
    k_xproj<<<gx, 256>>>(bih, bhh);
    for (int t = 0; t < TT; t++) k_step<<<512, 256>>>(t);
    k_fc<<<1, 128>>>(fcW, fcb, (float*)d_out);
}

// round 6
// speedup vs baseline: 1.9127x; 1.9127x over previous
#include <cuda_runtime.h>
#include <cuda_fp16.h>

#define BB 4
#define TT 32
#define NN 32
#define FF 16
#define GH 64
#define LSTM_IN 2048
#define LSTM_H 4096
#define G4 16384
#define EE 256

typedef unsigned long long u64t;

// Static scratch (no runtime allocation allowed)
__device__ float d_A[NN * NN];
__device__ float d_seq[BB * TT * LSTM_IN];        // GCN output, 1 MB
__device__ float d_XP[BB * TT * G4];              // x_proj, 8 MB
__device__ float d_H[2][BB * LSTM_H];             // hidden ping-pong
__device__ float d_C[BB * LSTM_H];                // cell state
__device__ __half d_Whh[(size_t)G4 * LSTM_H];     // fp16 W_hh, 134 MB
__device__ __half d_Wih[(size_t)G4 * LSTM_IN];    // fp16 W_ih, 67 MB

// ---- f32x2 packed-FMA helpers (full fp32 precision, 2x FFMA rate) ----------
__device__ __forceinline__ void fma2(u64t& d, u64t a, u64t b) {
    asm("fma.rn.f32x2 %0, %1, %2, %0;" : "+l"(d) : "l"(a), "l"(b));
}
__device__ __forceinline__ float2 upk(u64t v) {
    float2 f; asm("mov.b64 {%0, %1}, %2;" : "=f"(f.x), "=f"(f.y) : "l"(v)); return f;
}
// half2 -> packed f32x2
__device__ __forceinline__ u64t h2f2(unsigned h2) {
    u64t r;
    asm("{.reg .f16 lo, hi;\n\t"
        " .reg .f32 flo, fhi;\n\t"
        " mov.b32 {lo, hi}, %1;\n\t"
        " cvt.f32.f16 flo, lo;\n\t"
        " cvt.f32.f16 fhi, hi;\n\t"
        " mov.b64 %0, {flo, fhi};}"
        : "=l"(r) : "r"(h2));
    return r;
}

// ---------------------------------------------------------------------------
// fp32 -> fp16 conversion, 8 elements/thread
// ---------------------------------------------------------------------------
__global__ void k_cvt(const float* __restrict__ src, __half* __restrict__ dst, int n8) {
    int i = blockIdx.x * blockDim.x + threadIdx.x;
    if (i >= n8) return;
    const float4* s4 = (const float4*)src;
    float4 a = s4[(size_t)i * 2], b = s4[(size_t)i * 2 + 1];
    union { __half2 h[4]; uint4 u; } o;
    o.h[0] = __floats2half2_rn(a.x, a.y);
    o.h[1] = __floats2half2_rn(a.z, a.w);
    o.h[2] = __floats2half2_rn(b.x, b.y);
    o.h[3] = __floats2half2_rn(b.z, b.w);
    ((uint4*)dst)[i] = o.u;
}

// ---------------------------------------------------------------------------
// Dense adjacency (sym-norm + self loops); zero h/c. Runtime int32/64 sniff.
// ---------------------------------------------------------------------------
__global__ void k_setup(const long long* __restrict__ e64,
                        const int* __restrict__ e32) {
    __shared__ float sdeg[NN];
    __shared__ float sdinv[NN];
    __shared__ float sA[NN * NN];
    __shared__ int s_is64;
    int tid = threadIdx.x;

    if (tid == 0) s_is64 = 1;
    if (tid < NN) sdeg[tid] = 1.0f;
    for (int i = tid; i < NN * NN; i += blockDim.x) sA[i] = 0.f;
    __syncthreads();
    {
        long long v = e64[tid];
        if (v < 0 || v >= NN) atomicExch(&s_is64, 0);
    }
    __syncthreads();
    int is64 = s_is64;
    {
        int d = is64 ? (int)e64[EE + tid] : e32[EE + tid];
        if (d >= 0 && d < NN) atomicAdd(&sdeg[d], 1.0f);
    }
    __syncthreads();
    if (tid < NN) sdinv[tid] = rsqrtf(sdeg[tid]);
    __syncthreads();
    {
        int s = is64 ? (int)e64[tid]      : e32[tid];
        int d = is64 ? (int)e64[EE + tid] : e32[EE + tid];
        if (s >= 0 && s < NN && d >= 0 && d < NN)
            atomicAdd(&sA[d * NN + s], sdinv[s] * sdinv[d]);
    }
    __syncthreads();
    if (tid < NN) atomicAdd(&sA[tid * NN + tid], sdinv[tid] * sdinv[tid]);
    __syncthreads();
    for (int i = tid; i < NN * NN; i += blockDim.x) d_A[i] = sA[i];
    float* h = &d_H[0][0];
    for (int i = tid; i < 2 * BB * LSTM_H; i += blockDim.x) h[i] = 0.f;
    for (int i = tid; i < BB * LSTM_H; i += blockDim.x) d_C[i] = 0.f;
}

// ---------------------------------------------------------------------------
// Fused LayerNorm + GCN1 + GCN2 per (b,t) slice.
// ---------------------------------------------------------------------------
__global__ void k_gcn(const float* __restrict__ x,
                      const float* __restrict__ ln_g, const float* __restrict__ ln_b,
                      const float* __restrict__ W1, const float* __restrict__ b1,
                      const float* __restrict__ W2, const float* __restrict__ b2) {
    __shared__ float sA[NN * NN];
    __shared__ float sW1[FF * GH];
    __shared__ float sW2[GH * GH];
    __shared__ float sx[NN][FF];
    __shared__ float sb1[NN][GH];
    __shared__ float sb2[NN][GH];
    int tid = threadIdx.x;
    int bt = blockIdx.x;
    const float* xb = x + bt * NN * FF;

    for (int i = tid; i < NN * NN; i += 256) sA[i] = d_A[i];
    for (int i = tid; i < FF * GH; i += 256) sW1[i] = W1[i];
    for (int i = tid; i < GH * GH; i += 256) sW2[i] = W2[i];
    if (tid < NN) {
        float mu = 0.f;
        #pragma unroll
        for (int f = 0; f < FF; f++) mu += xb[tid * FF + f];
        mu *= (1.0f / FF);
        float var = 0.f;
        #pragma unroll
        for (int f = 0; f < FF; f++) { float d = xb[tid * FF + f] - mu; var += d * d; }
        var *= (1.0f / FF);
        float rs = rsqrtf(var + 1e-5f);
        #pragma unroll
        for (int f = 0; f < FF; f++)
            sx[tid][f] = (xb[tid * FF + f] - mu) * rs * ln_g[f] + ln_b[f];
    }
    __syncthreads();
    for (int i = tid; i < NN * GH; i += 256) {
        int n = i >> 6, g = i & 63;
        float s = 0.f;
        #pragma unroll
        for (int f = 0; f < FF; f++) s += sx[n][f] * sW1[f * GH + g];
        sb1[n][g] = s;
    }
    __syncthreads();
    for (int i = tid; i < NN * GH; i += 256) {
        int n = i >> 6, g = i & 63;
        float s = b1[g];
        #pragma unroll
        for (int m = 0; m < NN; m++) s += sA[n * NN + m] * sb1[m][g];
        sb2[n][g] = s;
    }
    __syncthreads();
    for (int i = tid; i < NN * GH; i += 256) {
        int n = i >> 6, g = i & 63;
        float s = 0.f;
        #pragma unroll
        for (int k = 0; k < GH; k++) s += sb2[n][k] * sW2[k * GH + g];
        sb1[n][g] = s;
    }
    __syncthreads();
    for (int i = tid; i < NN * GH; i += 256) {
        int n = i >> 6, g = i & 63;
        float s = b2[g];
        #pragma unroll
        for (int m = 0; m < NN; m++) s += sA[n * NN + m] * sb1[m][g];
        d_seq[bt * LSTM_IN + i] = s;
    }
}

// ---------------------------------------------------------------------------
// x_proj: warp = 2 rows x 16 bt, fp16 W_ih, f32x2 packed FMA; seq loaded as
// packed u64 pairs. grid (1024, 8) x 256 threads.
// ---------------------------------------------------------------------------
__global__ void __launch_bounds__(256) k_xproj(const float* __restrict__ bih,
                                               const float* __restrict__ bhh) {
    int lane = threadIdx.x & 31;
    int w = threadIdx.x >> 5;
    int row = blockIdx.x * 16 + w * 2;   // rows row, row+1
    int bt0 = blockIdx.y * 16;

    u64t acc[2][16];
    #pragma unroll
    for (int r = 0; r < 2; r++)
        #pragma unroll
        for (int j = 0; j < 16; j++) acc[r][j] = 0ull;

    const uint4* W0 = (const uint4*)(d_Wih + (size_t)row * LSTM_IN);
    const uint4* W1 = (const uint4*)(d_Wih + (size_t)(row + 1) * LSTM_IN);

    #pragma unroll 2
    for (int kc = 0; kc < 8; kc++) {
        int g = kc * 32 + lane;          // granule of 8 k
        uint4 wa = W0[g], wb = W1[g];
        u64t wA0 = h2f2(wa.x), wA1 = h2f2(wa.y), wA2 = h2f2(wa.z), wA3 = h2f2(wa.w);
        u64t wB0 = h2f2(wb.x), wB1 = h2f2(wb.y), wB2 = h2f2(wb.z), wB3 = h2f2(wb.w);
        #pragma unroll
        for (int j = 0; j < 16; j++) {
            const ulonglong2* S = (const ulonglong2*)(d_seq + (size_t)(bt0 + j) * LSTM_IN);
            ulonglong2 s0 = S[g * 2], s1 = S[g * 2 + 1];
            fma2(acc[0][j], wA0, s0.x); fma2(acc[0][j], wA1, s0.y);
            fma2(acc[0][j], wA2, s1.x); fma2(acc[0][j], wA3, s1.y);
            fma2(acc[1][j], wB0, s0.x); fma2(acc[1][j], wB1, s0.y);
            fma2(acc[1][j], wB2, s1.x); fma2(acc[1][j], wB3, s1.y);
        }
    }
    #pragma unroll
    for (int r = 0; r < 2; r++) {
        #pragma unroll
        for (int j = 0; j < 16; j++) {
            float2 f = upk(acc[r][j]);
            float v = f.x + f.y;
            #pragma unroll
            for (int o = 16; o; o >>= 1) v += __shfl_xor_sync(0xffffffffu, v, o);
            if (lane == 0) {
                int rr = row + r;
                d_XP[(size_t)(bt0 + j) * G4 + rr] = v + bih[rr] + bhh[rr];
            }
        }
    }
}

// ---------------------------------------------------------------------------
// One LSTM step, fp16 W_hh. 512 threads (16 warps), grid 128 -> single wave,
// all blocks resident (1/SM, 128-reg budget). Warp owns 8 gate-rows
// (wid + r*2048, r=0..7) = 2 complete units x 4 batches. h staged in smem
// (conflict-free float4/lane), W streamed as LDG.64; f32x2 accumulation.
// Live regs ~110: acc 64 + wb 16 + hA 16 + transients.
// ---------------------------------------------------------------------------
__global__ void __launch_bounds__(512, 1) k_step(int t) {
    extern __shared__ float sh[];        // 64 KB: h[4 batches][4096]
    int tid = threadIdx.x;
    const float* hin = d_H[t & 1];
    float* hout = d_H[(t + 1) & 1];

    // plain copy: 16384 floats = 512 threads x 8 float4
    {
        const float4* h4 = (const float4*)hin;
        float4* s4 = (float4*)sh;
        #pragma unroll
        for (int i = 0; i < 8; i++)
            s4[tid + i * 512] = h4[tid + i * 512];
    }
    __syncthreads();

    int wid = blockIdx.x * 16 + (tid >> 5);   // 0..2047
    int lane = tid & 31;

    // W row base: row = wid + r*2048; uint2 = 4 halfs; 1024 uint2 per row
    const uint2* Wp = (const uint2*)d_Whh + (size_t)wid * 1024;

    u64t acc[8][4];
    #pragma unroll
    for (int r = 0; r < 8; r++)
        #pragma unroll
        for (int b = 0; b < 4; b++) acc[r][b] = 0ull;

    const ulonglong2* shu = (const ulonglong2*)sh;  // float4 granules

    #pragma unroll 1
    for (int kc = 0; kc < 32; kc++) {
        int g = kc * 32 + lane;          // granule of 4 k
        uint2 wb[8];
        #pragma unroll
        for (int r = 0; r < 8; r++)
            wb[r] = Wp[(size_t)r * (2048u * 1024u) + g];
        ulonglong2 hA[4];
        #pragma unroll
        for (int b = 0; b < 4; b++)
            hA[b] = shu[b * 1024 + g];
        #pragma unroll
        for (int r = 0; r < 8; r++) {
            u64t w0 = h2f2(wb[r].x), w1 = h2f2(wb[r].y);
            #pragma unroll
            for (int b = 0; b < 4; b++) {
                fma2(acc[r][b], w0, hA[b].x);
                fma2(acc[r][b], w1, hA[b].y);
            }
        }
    }

    float fa[8][4];
    #pragma unroll
    for (int r = 0; r < 8; r++)
        #pragma unroll
        for (int b = 0; b < 4; b++) {
            float2 f = upk(acc[r][b]);
            float v = f.x + f.y;
            #pragma unroll
            for (int o = 16; o; o >>= 1) v += __shfl_xor_sync(0xffffffffu, v, o);
            fa[r][b] = v;
        }

    if (lane == 0) {
        #pragma unroll
        for (int j = 0; j < 2; j++) {            // two units per warp
            int u = wid + j * 2048;
            #pragma unroll
            for (int b = 0; b < 4; b++) {
                size_t xb = ((size_t)b * TT + t) * G4;
                float gi = fa[j][b]     + d_XP[xb + u];
                float gf = fa[j + 2][b] + d_XP[xb + u + 4096];
                float gg = fa[j + 4][b] + d_XP[xb + u + 8192];
                float go = fa[j + 6][b] + d_XP[xb + u + 12288];
                float si = 1.f / (1.f + expf(-gi));
                float sf = 1.f / (1.f + expf(-gf));
                float so = 1.f / (1.f + expf(-go));
                float c = sf * d_C[b * LSTM_H + u] + si * tanhf(gg);
                d_C[b * LSTM_H + u] = c;
                hout[b * LSTM_H + u] = so * tanhf(c);
            }
        }
    }
}

// ---------------------------------------------------------------------------
// Final FC
// ---------------------------------------------------------------------------
__global__ void k_fc(const float* __restrict__ fcW, const float* __restrict__ fcb,
                     float* __restrict__ out) {
    int i = threadIdx.x;  // 0..127
    int b = i >> 5, n = i & 31;
    const float* h = &d_H[0][0] + b * LSTM_H + n * 128;  // T=32 -> parity 0
    float s = 0.f;
    #pragma unroll
    for (int l = 0; l < 128; l++) s += h[l] * fcW[l];
    out[i] = s + fcb[0];
}

extern "C" void kernel_launch(void* const* d_in, const int* in_sizes, int n_in,
                              void* d_out, int out_size) {
    const float* x       = (const float*)d_in[0];
    const void*  ei      = d_in[1];
    const float* ln_g    = (const float*)d_in[2];
    const float* ln_b    = (const float*)d_in[3];
    const float* W1      = (const float*)d_in[4];
    const float* b1      = (const float*)d_in[5];
    const float* W2      = (const float*)d_in[6];
    const float* b2      = (const float*)d_in[7];
    const float* Wih     = (const float*)d_in[8];
    const float* bih     = (const float*)d_in[9];
    const float* Whh     = (const float*)d_in[10];
    const float* bhh     = (const float*)d_in[11];
    const float* fcW     = (const float*)d_in[12];
    const float* fcb     = (const float*)d_in[13];

    __half* whh_h = nullptr;  cudaGetSymbolAddress((void**)&whh_h, d_Whh);
    __half* wih_h = nullptr;  cudaGetSymbolAddress((void**)&wih_h, d_Wih);

    static int smem_set = 0;
    if (!smem_set) {
        cudaFuncSetAttribute(k_step, cudaFuncAttributeMaxDynamicSharedMemorySize, 65536);
        smem_set = 1;
    }

    k_setup<<<1, 256>>>((const long long*)ei, (const int*)ei);
    k_cvt<<<(G4 * LSTM_H / 8 + 255) / 256, 256>>>(Whh, whh_h, G4 * LSTM_H / 8);
    k_cvt<<<(G4 * LSTM_IN / 8 + 255) / 256, 256>>>(Wih, wih_h, G4 * LSTM_IN / 8);
    k_gcn<<<BB * TT, 256>>>(x, ln_g, ln_b, W1, b1, W2, b2);
    dim3 gx(G4 / 16, 8);
    k_xproj<<<gx, 256>>>(bih, bhh);
    for (int t = 0; t < TT; t++) k_step<<<128, 512, 65536>>>(t);
    k_fc<<<1, 128>>>(fcW, fcb, (float*)d_out);
}

// round 7
// speedup vs baseline: 2.1913x; 1.1456x over previous
#include <cuda_runtime.h>
#include <cuda_fp16.h>

#define BB 4
#define TT 32
#define NN 32
#define FF 16
#define GH 64
#define LSTM_IN 2048
#define LSTM_H 4096
#define G4 16384
#define EE 256

typedef unsigned long long u64t;

// Static scratch (no runtime allocation allowed)
__device__ float d_A[NN * NN];
__device__ float d_seq[BB * TT * LSTM_IN];        // GCN output, 1 MB
__device__ float d_XP[BB * TT * G4];              // x_proj, 8 MB
__device__ float d_H[2][BB * LSTM_H];             // hidden ping-pong
__device__ float d_C[BB * LSTM_H];                // cell state
__device__ __half d_Whh[(size_t)G4 * LSTM_H];     // fp16 W_hh, 134 MB

// ---- f32x2 packed-FMA helpers (full fp32 precision, 2x FFMA rate) ----------
__device__ __forceinline__ void fma2(u64t& d, u64t a, u64t b) {
    asm("fma.rn.f32x2 %0, %1, %2, %0;" : "+l"(d) : "l"(a), "l"(b));
}
__device__ __forceinline__ u64t pkf2(float x, float y) {
    u64t r; asm("mov.b64 %0, {%1, %2};" : "=l"(r) : "f"(x), "f"(y)); return r;
}
__device__ __forceinline__ float2 upk(u64t v) {
    float2 f; asm("mov.b64 {%0, %1}, %2;" : "=f"(f.x), "=f"(f.y) : "l"(v)); return f;
}
// half2 -> packed f32x2
__device__ __forceinline__ u64t h2f2(unsigned h2) {
    u64t r;
    asm("{.reg .f16 lo, hi;\n\t"
        " .reg .f32 flo, fhi;\n\t"
        " mov.b32 {lo, hi}, %1;\n\t"
        " cvt.f32.f16 flo, lo;\n\t"
        " cvt.f32.f16 fhi, hi;\n\t"
        " mov.b64 %0, {flo, fhi};}"
        : "=l"(r) : "r"(h2));
    return r;
}

// ---------------------------------------------------------------------------
// fp32 -> fp16 conversion, 8 elements/thread (W_hh only)
// ---------------------------------------------------------------------------
__global__ void k_cvt(const float* __restrict__ src, __half* __restrict__ dst, int n8) {
    int i = blockIdx.x * blockDim.x + threadIdx.x;
    if (i >= n8) return;
    const float4* s4 = (const float4*)src;
    float4 a = s4[(size_t)i * 2], b = s4[(size_t)i * 2 + 1];
    union { __half2 h[4]; uint4 u; } o;
    o.h[0] = __floats2half2_rn(a.x, a.y);
    o.h[1] = __floats2half2_rn(a.z, a.w);
    o.h[2] = __floats2half2_rn(b.x, b.y);
    o.h[3] = __floats2half2_rn(b.z, b.w);
    ((uint4*)dst)[i] = o.u;
}

// ---------------------------------------------------------------------------
// Dense adjacency (sym-norm + self loops); zero h/c. Runtime int32/64 sniff.
// ---------------------------------------------------------------------------
__global__ void k_setup(const long long* __restrict__ e64,
                        const int* __restrict__ e32) {
    __shared__ float sdeg[NN];
    __shared__ float sdinv[NN];
    __shared__ float sA[NN * NN];
    __shared__ int s_is64;
    int tid = threadIdx.x;

    if (tid == 0) s_is64 = 1;
    if (tid < NN) sdeg[tid] = 1.0f;
    for (int i = tid; i < NN * NN; i += blockDim.x) sA[i] = 0.f;
    __syncthreads();
    {
        long long v = e64[tid];
        if (v < 0 || v >= NN) atomicExch(&s_is64, 0);
    }
    __syncthreads();
    int is64 = s_is64;
    {
        int d = is64 ? (int)e64[EE + tid] : e32[EE + tid];
        if (d >= 0 && d < NN) atomicAdd(&sdeg[d], 1.0f);
    }
    __syncthreads();
    if (tid < NN) sdinv[tid] = rsqrtf(sdeg[tid]);
    __syncthreads();
    {
        int s = is64 ? (int)e64[tid]      : e32[tid];
        int d = is64 ? (int)e64[EE + tid] : e32[EE + tid];
        if (s >= 0 && s < NN && d >= 0 && d < NN)
            atomicAdd(&sA[d * NN + s], sdinv[s] * sdinv[d]);
    }
    __syncthreads();
    if (tid < NN) atomicAdd(&sA[tid * NN + tid], sdinv[tid] * sdinv[tid]);
    __syncthreads();
    for (int i = tid; i < NN * NN; i += blockDim.x) d_A[i] = sA[i];
    float* h = &d_H[0][0];
    for (int i = tid; i < 2 * BB * LSTM_H; i += blockDim.x) h[i] = 0.f;
    for (int i = tid; i < BB * LSTM_H; i += blockDim.x) d_C[i] = 0.f;
}

// ---------------------------------------------------------------------------
// Fused LayerNorm + GCN1 + GCN2 per (b,t) slice.
// ---------------------------------------------------------------------------
__global__ void k_gcn(const float* __restrict__ x,
                      const float* __restrict__ ln_g, const float* __restrict__ ln_b,
                      const float* __restrict__ W1, const float* __restrict__ b1,
                      const float* __restrict__ W2, const float* __restrict__ b2) {
    __shared__ float sA[NN * NN];
    __shared__ float sW1[FF * GH];
    __shared__ float sW2[GH * GH];
    __shared__ float sx[NN][FF];
    __shared__ float sb1[NN][GH];
    __shared__ float sb2[NN][GH];
    int tid = threadIdx.x;
    int bt = blockIdx.x;
    const float* xb = x + bt * NN * FF;

    for (int i = tid; i < NN * NN; i += 256) sA[i] = d_A[i];
    for (int i = tid; i < FF * GH; i += 256) sW1[i] = W1[i];
    for (int i = tid; i < GH * GH; i += 256) sW2[i] = W2[i];
    if (tid < NN) {
        float mu = 0.f;
        #pragma unroll
        for (int f = 0; f < FF; f++) mu += xb[tid * FF + f];
        mu *= (1.0f / FF);
        float var = 0.f;
        #pragma unroll
        for (int f = 0; f < FF; f++) { float d = xb[tid * FF + f] - mu; var += d * d; }
        var *= (1.0f / FF);
        float rs = rsqrtf(var + 1e-5f);
        #pragma unroll
        for (int f = 0; f < FF; f++)
            sx[tid][f] = (xb[tid * FF + f] - mu) * rs * ln_g[f] + ln_b[f];
    }
    __syncthreads();
    for (int i = tid; i < NN * GH; i += 256) {
        int n = i >> 6, g = i & 63;
        float s = 0.f;
        #pragma unroll
        for (int f = 0; f < FF; f++) s += sx[n][f] * sW1[f * GH + g];
        sb1[n][g] = s;
    }
    __syncthreads();
    for (int i = tid; i < NN * GH; i += 256) {
        int n = i >> 6, g = i & 63;
        float s = b1[g];
        #pragma unroll
        for (int m = 0; m < NN; m++) s += sA[n * NN + m] * sb1[m][g];
        sb2[n][g] = s;
    }
    __syncthreads();
    for (int i = tid; i < NN * GH; i += 256) {
        int n = i >> 6, g = i & 63;
        float s = 0.f;
        #pragma unroll
        for (int k = 0; k < GH; k++) s += sb2[n][k] * sW2[k * GH + g];
        sb1[n][g] = s;
    }
    __syncthreads();
    for (int i = tid; i < NN * GH; i += 256) {
        int n = i >> 6, g = i & 63;
        float s = b2[g];
        #pragma unroll
        for (int m = 0; m < NN; m++) s += sA[n * NN + m] * sb1[m][g];
        d_seq[bt * LSTM_IN + i] = s;
    }
}

// ---------------------------------------------------------------------------
// x_proj v3: smem-tiled GEMM. C[row=16384][bt=128] = W[row][k] . S[bt][k].
// Grid 128 (row tiles of 128), block 512 = 16 ty x 32 tx.
// Thread computes 8 rows x 4 bt. W read ONCE as fp32 (no cvt). K chunks of 64.
// smem: sW[k][row] broadcast-packed u64 (64KB) + sS[k][bt] f32 pad 132 (33.8KB).
// ---------------------------------------------------------------------------
#define XSMEM (64 * 128 * 8 + 64 * 132 * 4)
__global__ void __launch_bounds__(512) k_xproj(const float* __restrict__ Wih,
                                               const float* __restrict__ bih,
                                               const float* __restrict__ bhh) {
    extern __shared__ char xsm[];
    u64t* sW = (u64t*)xsm;                       // [k][128 rows]
    float* sS = (float*)(xsm + 64 * 128 * 8);    // [k][132]
    int tid = threadIdx.x;
    int m0 = blockIdx.x * 128;
    int ty = tid >> 5;          // rows ty*8..+7
    int tx = tid & 31;          // bts tx*4..+3

    u64t acc[8][2];
    #pragma unroll
    for (int r = 0; r < 8; r++) { acc[r][0] = 0ull; acc[r][1] = 0ull; }

    int lr = tid >> 2;                  // load row / bt: 0..127
    int lk = (tid & 3) * 16;            // 16 k per thread

    for (int kc = 0; kc < 32; kc++) {
        __syncthreads();
        // W tile: 128 rows x 64 k, fp32 -> broadcast-packed u64
        {
            const float4* src = (const float4*)(Wih + (size_t)(m0 + lr) * LSTM_IN + kc * 64 + lk);
            #pragma unroll
            for (int i = 0; i < 4; i++) {
                float4 v = src[i];
                int k = lk + i * 4;
                sW[(k + 0) * 128 + lr] = pkf2(v.x, v.x);
                sW[(k + 1) * 128 + lr] = pkf2(v.y, v.y);
                sW[(k + 2) * 128 + lr] = pkf2(v.z, v.z);
                sW[(k + 3) * 128 + lr] = pkf2(v.w, v.w);
            }
        }
        // S tile: 128 bt x 64 k -> sS[k][bt]
        {
            const float4* src = (const float4*)(d_seq + (size_t)lr * LSTM_IN + kc * 64 + lk);
            #pragma unroll
            for (int i = 0; i < 4; i++) {
                float4 v = src[i];
                int k = lk + i * 4;
                sS[(k + 0) * 132 + lr] = v.x;
                sS[(k + 1) * 132 + lr] = v.y;
                sS[(k + 2) * 132 + lr] = v.z;
                sS[(k + 3) * 132 + lr] = v.w;
            }
        }
        __syncthreads();
        #pragma unroll 4
        for (int k = 0; k < 64; k++) {
            const ulonglong2* wr = (const ulonglong2*)(sW + k * 128 + ty * 8);
            ulonglong2 w01 = wr[0], w23 = wr[1], w45 = wr[2], w67 = wr[3];
            ulonglong2 sp = *(const ulonglong2*)(sS + k * 132 + tx * 4);
            fma2(acc[0][0], w01.x, sp.x); fma2(acc[0][1], w01.x, sp.y);
            fma2(acc[1][0], w01.y, sp.x); fma2(acc[1][1], w01.y, sp.y);
            fma2(acc[2][0], w23.x, sp.x); fma2(acc[2][1], w23.x, sp.y);
            fma2(acc[3][0], w23.y, sp.x); fma2(acc[3][1], w23.y, sp.y);
            fma2(acc[4][0], w45.x, sp.x); fma2(acc[4][1], w45.x, sp.y);
            fma2(acc[5][0], w45.y, sp.x); fma2(acc[5][1], w45.y, sp.y);
            fma2(acc[6][0], w67.x, sp.x); fma2(acc[6][1], w67.x, sp.y);
            fma2(acc[7][0], w67.y, sp.x); fma2(acc[7][1], w67.y, sp.y);
        }
    }

    // epilogue: add bias, store to d_XP[bt][row]
    float bias[8];
    #pragma unroll
    for (int r = 0; r < 8; r++) {
        int row = m0 + ty * 8 + r;
        bias[r] = bih[row] + bhh[row];
    }
    #pragma unroll
    for (int p = 0; p < 2; p++) {
        #pragma unroll
        for (int h = 0; h < 2; h++) {
            int bt = tx * 4 + p * 2 + h;
            float v[8];
            #pragma unroll
            for (int r = 0; r < 8; r++) {
                float2 f = upk(acc[r][p]);
                v[r] = (h ? f.y : f.x) + bias[r];
            }
            float4* dst = (float4*)(d_XP + (size_t)bt * G4 + m0 + ty * 8);
            dst[0] = make_float4(v[0], v[1], v[2], v[3]);
            dst[1] = make_float4(v[4], v[5], v[6], v[7]);
        }
    }
}

// ---------------------------------------------------------------------------
// One LSTM step, fp16 W_hh. 512 threads (16 warps), grid 128 -> single wave.
// Warp owns 8 gate-rows (wid + r*2048) = 2 units x 4 batches. h staged in smem;
// W streamed as LDG.64 with next-granule prefetch (double the bytes in flight).
// ---------------------------------------------------------------------------
__global__ void __launch_bounds__(512, 1) k_step(int t) {
    extern __shared__ float sh[];        // 64 KB: h[4 batches][4096]
    int tid = threadIdx.x;
    const float* hin = d_H[t & 1];
    float* hout = d_H[(t + 1) & 1];

    {
        const float4* h4 = (const float4*)hin;
        float4* s4 = (float4*)sh;
        #pragma unroll
        for (int i = 0; i < 8; i++)
            s4[tid + i * 512] = h4[tid + i * 512];
    }
    __syncthreads();

    int wid = blockIdx.x * 16 + (tid >> 5);   // 0..2047
    int lane = tid & 31;

    const uint2* Wp = (const uint2*)d_Whh + (size_t)wid * 1024;

    u64t acc[8][4];
    #pragma unroll
    for (int r = 0; r < 8; r++)
        #pragma unroll
        for (int b = 0; b < 4; b++) acc[r][b] = 0ull;

    const ulonglong2* shu = (const ulonglong2*)sh;

    uint2 cur[8];
    #pragma unroll
    for (int r = 0; r < 8; r++)
        cur[r] = Wp[(size_t)r * (2048u * 1024u) + lane];

    #pragma unroll 2
    for (int kc = 0; kc < 32; kc++) {
        int g = kc * 32 + lane;
        uint2 nxt[8];
        if (kc < 31) {
            #pragma unroll
            for (int r = 0; r < 8; r++)
                nxt[r] = Wp[(size_t)r * (2048u * 1024u) + g + 32];
        }
        ulonglong2 hA[4];
        #pragma unroll
        for (int b = 0; b < 4; b++)
            hA[b] = shu[b * 1024 + g];
        #pragma unroll
        for (int r = 0; r < 8; r++) {
            u64t w0 = h2f2(cur[r].x), w1 = h2f2(cur[r].y);
            #pragma unroll
            for (int b = 0; b < 4; b++) {
                fma2(acc[r][b], w0, hA[b].x);
                fma2(acc[r][b], w1, hA[b].y);
            }
        }
        #pragma unroll
        for (int r = 0; r < 8; r++) cur[r] = nxt[r];
    }

    float fa[8][4];
    #pragma unroll
    for (int r = 0; r < 8; r++)
        #pragma unroll
        for (int b = 0; b < 4; b++) {
            float2 f = upk(acc[r][b]);
            float v = f.x + f.y;
            #pragma unroll
            for (int o = 16; o; o >>= 1) v += __shfl_xor_sync(0xffffffffu, v, o);
            fa[r][b] = v;
        }

    if (lane == 0) {
        #pragma unroll
        for (int j = 0; j < 2; j++) {
            int u = wid + j * 2048;
            #pragma unroll
            for (int b = 0; b < 4; b++) {
                size_t xb = ((size_t)b * TT + t) * G4;
                float gi = fa[j][b]     + d_XP[xb + u];
                float gf = fa[j + 2][b] + d_XP[xb + u + 4096];
                float gg = fa[j + 4][b] + d_XP[xb + u + 8192];
                float go = fa[j + 6][b] + d_XP[xb + u + 12288];
                float si = 1.f / (1.f + expf(-gi));
                float sf = 1.f / (1.f + expf(-gf));
                float so = 1.f / (1.f + expf(-go));
                float c = sf * d_C[b * LSTM_H + u] + si * tanhf(gg);
                d_C[b * LSTM_H + u] = c;
                hout[b * LSTM_H + u] = so * tanhf(c);
            }
        }
    }
}

// ---------------------------------------------------------------------------
// Final FC
// ---------------------------------------------------------------------------
__global__ void k_fc(const float* __restrict__ fcW, const float* __restrict__ fcb,
                     float* __restrict__ out) {
    int i = threadIdx.x;  // 0..127
    int b = i >> 5, n = i & 31;
    const float* h = &d_H[0][0] + b * LSTM_H + n * 128;  // T=32 -> parity 0
    float s = 0.f;
    #pragma unroll
    for (int l = 0; l < 128; l++) s += h[l] * fcW[l];
    out[i] = s + fcb[0];
}

extern "C" void kernel_launch(void* const* d_in, const int* in_sizes, int n_in,
                              void* d_out, int out_size) {
    const float* x       = (const float*)d_in[0];
    const void*  ei      = d_in[1];
    const float* ln_g    = (const float*)d_in[2];
    const float* ln_b    = (const float*)d_in[3];
    const float* W1      = (const float*)d_in[4];
    const float* b1      = (const float*)d_in[5];
    const float* W2      = (const float*)d_in[6];
    const float* b2      = (const float*)d_in[7];
    const float* Wih     = (const float*)d_in[8];
    const float* bih     = (const float*)d_in[9];
    const float* Whh     = (const float*)d_in[10];
    const float* bhh     = (const float*)d_in[11];
    const float* fcW     = (const float*)d_in[12];
    const float* fcb     = (const float*)d_in[13];

    __half* whh_h = nullptr;  cudaGetSymbolAddress((void**)&whh_h, d_Whh);

    static int attr_set = 0;
    if (!attr_set) {
        cudaFuncSetAttribute(k_step, cudaFuncAttributeMaxDynamicSharedMemorySize, 65536);
        cudaFuncSetAttribute(k_xproj, cudaFuncAttributeMaxDynamicSharedMemorySize, XSMEM);
        attr_set = 1;
    }

    k_setup<<<1, 256>>>((const long long*)ei, (const int*)ei);
    k_cvt<<<(G4 * LSTM_H / 8 + 255) / 256, 256>>>(Whh, whh_h, G4 * LSTM_H / 8);
    k_gcn<<<BB * TT, 256>>>(x, ln_g, ln_b, W1, b1, W2, b2);
    k_xproj<<<128, 512, XSMEM>>>(Wih, bih, bhh);
    for (int t = 0; t < TT; t++) k_step<<<128, 512, 65536>>>(t);
    k_fc<<<1, 128>>>(fcW, fcb, (float*)d_out);
}

// round 8
// speedup vs baseline: 2.3980x; 1.0944x over previous
#include <cuda_runtime.h>
#include <cuda_fp16.h>

#define BB 4
#define TT 32
#define NN 32
#define FF 16
#define GH 64
#define LSTM_IN 2048
#define LSTM_H 4096
#define G4 16384
#define EE 256

typedef unsigned long long u64t;

// Static scratch (no runtime allocation allowed)
__device__ float d_A[NN * NN];
__device__ float d_seq[BB * TT * LSTM_IN];        // GCN output, 1 MB
__device__ float d_XP[BB * TT * G4];              // x_proj, 8 MB
__device__ float d_H[2][BB * LSTM_H];             // hidden ping-pong
__device__ float d_C[BB * LSTM_H];                // cell state
// W_hh fp16, permuted warp-major: [wid 2048][kc 32][r 8][lane 32] uint2 (4 halfs)
__device__ uint2 d_Wp[2048 * 32 * 8 * 32];

// ---- f32x2 packed-FMA helpers (full fp32 precision, 2x FFMA rate) ----------
__device__ __forceinline__ void fma2(u64t& d, u64t a, u64t b) {
    asm("fma.rn.f32x2 %0, %1, %2, %0;" : "+l"(d) : "l"(a), "l"(b));
}
__device__ __forceinline__ u64t pkf2(float x, float y) {
    u64t r; asm("mov.b64 %0, {%1, %2};" : "=l"(r) : "f"(x), "f"(y)); return r;
}
__device__ __forceinline__ float2 upk(u64t v) {
    float2 f; asm("mov.b64 {%0, %1}, %2;" : "=f"(f.x), "=f"(f.y) : "l"(v)); return f;
}
// half2 -> packed f32x2
__device__ __forceinline__ u64t h2f2(unsigned h2) {
    u64t r;
    asm("{.reg .f16 lo, hi;\n\t"
        " .reg .f32 flo, fhi;\n\t"
        " mov.b32 {lo, hi}, %1;\n\t"
        " cvt.f32.f16 flo, lo;\n\t"
        " cvt.f32.f16 fhi, hi;\n\t"
        " mov.b64 %0, {flo, fhi};}"
        : "=l"(r) : "r"(h2));
    return r;
}

// ---------------------------------------------------------------------------
// fp32 -> fp16 conversion + warp-major permutation of W_hh.
// Output uint2 i = ((wid*32 + kc)*8 + r)*32 + lane  <-  src row (wid + r*2048),
// k range [(kc*32+lane)*4, +4).
// ---------------------------------------------------------------------------
__global__ void k_cvt2(const float* __restrict__ src) {
    int i = blockIdx.x * blockDim.x + threadIdx.x;   // 0 .. 16777215
    int lane = i & 31;
    int r = (i >> 5) & 7;
    int kc = (i >> 8) & 31;
    int wid = i >> 13;
    int row = wid + r * 2048;
    float4 v = *(const float4*)(src + (size_t)row * LSTM_H + (kc * 32 + lane) * 4);
    union { __half2 h[2]; uint2 u; } o;
    o.h[0] = __floats2half2_rn(v.x, v.y);
    o.h[1] = __floats2half2_rn(v.z, v.w);
    d_Wp[i] = o.u;
}

// ---------------------------------------------------------------------------
// Dense adjacency (sym-norm + self loops); zero h/c. Runtime int32/64 sniff.
// ---------------------------------------------------------------------------
__global__ void k_setup(const long long* __restrict__ e64,
                        const int* __restrict__ e32) {
    __shared__ float sdeg[NN];
    __shared__ float sdinv[NN];
    __shared__ float sA[NN * NN];
    __shared__ int s_is64;
    int tid = threadIdx.x;

    if (tid == 0) s_is64 = 1;
    if (tid < NN) sdeg[tid] = 1.0f;
    for (int i = tid; i < NN * NN; i += blockDim.x) sA[i] = 0.f;
    __syncthreads();
    {
        long long v = e64[tid];
        if (v < 0 || v >= NN) atomicExch(&s_is64, 0);
    }
    __syncthreads();
    int is64 = s_is64;
    {
        int d = is64 ? (int)e64[EE + tid] : e32[EE + tid];
        if (d >= 0 && d < NN) atomicAdd(&sdeg[d], 1.0f);
    }
    __syncthreads();
    if (tid < NN) sdinv[tid] = rsqrtf(sdeg[tid]);
    __syncthreads();
    {
        int s = is64 ? (int)e64[tid]      : e32[tid];
        int d = is64 ? (int)e64[EE + tid] : e32[EE + tid];
        if (s >= 0 && s < NN && d >= 0 && d < NN)
            atomicAdd(&sA[d * NN + s], sdinv[s] * sdinv[d]);
    }
    __syncthreads();
    if (tid < NN) atomicAdd(&sA[tid * NN + tid], sdinv[tid] * sdinv[tid]);
    __syncthreads();
    for (int i = tid; i < NN * NN; i += blockDim.x) d_A[i] = sA[i];
    float* h = &d_H[0][0];
    for (int i = tid; i < 2 * BB * LSTM_H; i += blockDim.x) h[i] = 0.f;
    for (int i = tid; i < BB * LSTM_H; i += blockDim.x) d_C[i] = 0.f;
}

// ---------------------------------------------------------------------------
// Fused LayerNorm + GCN1 + GCN2 per (b,t) slice.
// ---------------------------------------------------------------------------
__global__ void k_gcn(const float* __restrict__ x,
                      const float* __restrict__ ln_g, const float* __restrict__ ln_b,
                      const float* __restrict__ W1, const float* __restrict__ b1,
                      const float* __restrict__ W2, const float* __restrict__ b2) {
    __shared__ float sA[NN * NN];
    __shared__ float sW1[FF * GH];
    __shared__ float sW2[GH * GH];
    __shared__ float sx[NN][FF];
    __shared__ float sb1[NN][GH];
    __shared__ float sb2[NN][GH];
    int tid = threadIdx.x;
    int bt = blockIdx.x;
    const float* xb = x + bt * NN * FF;

    for (int i = tid; i < NN * NN; i += 256) sA[i] = d_A[i];
    for (int i = tid; i < FF * GH; i += 256) sW1[i] = W1[i];
    for (int i = tid; i < GH * GH; i += 256) sW2[i] = W2[i];
    if (tid < NN) {
        float mu = 0.f;
        #pragma unroll
        for (int f = 0; f < FF; f++) mu += xb[tid * FF + f];
        mu *= (1.0f / FF);
        float var = 0.f;
        #pragma unroll
        for (int f = 0; f < FF; f++) { float d = xb[tid * FF + f] - mu; var += d * d; }
        var *= (1.0f / FF);
        float rs = rsqrtf(var + 1e-5f);
        #pragma unroll
        for (int f = 0; f < FF; f++)
            sx[tid][f] = (xb[tid * FF + f] - mu) * rs * ln_g[f] + ln_b[f];
    }
    __syncthreads();
    for (int i = tid; i < NN * GH; i += 256) {
        int n = i >> 6, g = i & 63;
        float s = 0.f;
        #pragma unroll
        for (int f = 0; f < FF; f++) s += sx[n][f] * sW1[f * GH + g];
        sb1[n][g] = s;
    }
    __syncthreads();
    for (int i = tid; i < NN * GH; i += 256) {
        int n = i >> 6, g = i & 63;
        float s = b1[g];
        #pragma unroll
        for (int m = 0; m < NN; m++) s += sA[n * NN + m] * sb1[m][g];
        sb2[n][g] = s;
    }
    __syncthreads();
    for (int i = tid; i < NN * GH; i += 256) {
        int n = i >> 6, g = i & 63;
        float s = 0.f;
        #pragma unroll
        for (int k = 0; k < GH; k++) s += sb2[n][k] * sW2[k * GH + g];
        sb1[n][g] = s;
    }
    __syncthreads();
    for (int i = tid; i < NN * GH; i += 256) {
        int n = i >> 6, g = i & 63;
        float s = b2[g];
        #pragma unroll
        for (int m = 0; m < NN; m++) s += sA[n * NN + m] * sb1[m][g];
        d_seq[bt * LSTM_IN + i] = s;
    }
}

// ---------------------------------------------------------------------------
// x_proj v4: smem-tiled GEMM, row-pair f32x2 accumulators.
// C[row=16384][bt=128] = W[row][k] . S[bt][k]. Grid 128, block 512 = 16ty x 32tx.
// Thread: 8 rows (4 pairs) x 4 bt. sW plain f32 [64][132]; sS f32 [64][132].
// Inner k: 2 LDS.128 (w pairs) + 1 LDS.128 (s) + 4 mov + 16 fma2.
// ---------------------------------------------------------------------------
#define XP_PAD 132
#define XSMEM (2 * 64 * XP_PAD * 4)
__global__ void __launch_bounds__(512) k_xproj(const float* __restrict__ Wih,
                                               const float* __restrict__ bih,
                                               const float* __restrict__ bhh) {
    extern __shared__ float xsm[];
    float* sW = xsm;                     // [k][132] rows-major-in-k
    float* sS = xsm + 64 * XP_PAD;       // [k][132]
    int tid = threadIdx.x;
    int m0 = blockIdx.x * 128;
    int ty = tid >> 5;          // row block: rows ty*8..+7
    int tx = tid & 31;          // bt block: tx*4..+3

    u64t acc[4][4];             // [row-pair][bt]
    #pragma unroll
    for (int p = 0; p < 4; p++)
        #pragma unroll
        for (int b = 0; b < 4; b++) acc[p][b] = 0ull;

    int lr = tid >> 2;                  // load row / bt: 0..127
    int lk = (tid & 3) * 16;            // 16 k per thread

    for (int kc = 0; kc < 32; kc++) {
        __syncthreads();
        // W tile: 128 rows x 64 k fp32 -> sW[k][row]
        {
            const float4* src = (const float4*)(Wih + (size_t)(m0 + lr) * LSTM_IN + kc * 64 + lk);
            #pragma unroll
            for (int i = 0; i < 4; i++) {
                float4 v = src[i];
                int k = lk + i * 4;
                sW[(k + 0) * XP_PAD + lr] = v.x;
                sW[(k + 1) * XP_PAD + lr] = v.y;
                sW[(k + 2) * XP_PAD + lr] = v.z;
                sW[(k + 3) * XP_PAD + lr] = v.w;
            }
        }
        // S tile: 128 bt x 64 k -> sS[k][bt]
        {
            const float4* src = (const float4*)(d_seq + (size_t)lr * LSTM_IN + kc * 64 + lk);
            #pragma unroll
            for (int i = 0; i < 4; i++) {
                float4 v = src[i];
                int k = lk + i * 4;
                sS[(k + 0) * XP_PAD + lr] = v.x;
                sS[(k + 1) * XP_PAD + lr] = v.y;
                sS[(k + 2) * XP_PAD + lr] = v.z;
                sS[(k + 3) * XP_PAD + lr] = v.w;
            }
        }
        __syncthreads();
        #pragma unroll 4
        for (int k = 0; k < 64; k++) {
            // 8 rows = 4 (row,row+1) f32 pairs, loaded directly as u64
            const ulonglong2* wr = (const ulonglong2*)(sW + k * XP_PAD + ty * 8);
            ulonglong2 wA = wr[0], wB = wr[1];        // pairs p0,p1,p2,p3
            float4 s4 = *(const float4*)(sS + k * XP_PAD + tx * 4);
            u64t b0 = pkf2(s4.x, s4.x), b1 = pkf2(s4.y, s4.y);
            u64t b2 = pkf2(s4.z, s4.z), b3 = pkf2(s4.w, s4.w);
            fma2(acc[0][0], wA.x, b0); fma2(acc[0][1], wA.x, b1);
            fma2(acc[0][2], wA.x, b2); fma2(acc[0][3], wA.x, b3);
            fma2(acc[1][0], wA.y, b0); fma2(acc[1][1], wA.y, b1);
            fma2(acc[1][2], wA.y, b2); fma2(acc[1][3], wA.y, b3);
            fma2(acc[2][0], wB.x, b0); fma2(acc[2][1], wB.x, b1);
            fma2(acc[2][2], wB.x, b2); fma2(acc[2][3], wB.x, b3);
            fma2(acc[3][0], wB.y, b0); fma2(acc[3][1], wB.y, b1);
            fma2(acc[3][2], wB.y, b2); fma2(acc[3][3], wB.y, b3);
        }
    }

    // epilogue: add bias, store to d_XP[bt][row]
    float bias[8];
    #pragma unroll
    for (int r = 0; r < 8; r++) {
        int row = m0 + ty * 8 + r;
        bias[r] = bih[row] + bhh[row];
    }
    #pragma unroll
    for (int b = 0; b < 4; b++) {
        int bt = tx * 4 + b;
        float v[8];
        #pragma unroll
        for (int p = 0; p < 4; p++) {
            float2 f = upk(acc[p][b]);
            v[p * 2 + 0] = f.x + bias[p * 2 + 0];
            v[p * 2 + 1] = f.y + bias[p * 2 + 1];
        }
        float4* dst = (float4*)(d_XP + (size_t)bt * G4 + m0 + ty * 8);
        dst[0] = make_float4(v[0], v[1], v[2], v[3]);
        dst[1] = make_float4(v[4], v[5], v[6], v[7]);
    }
}

// ---------------------------------------------------------------------------
// One LSTM step. W in warp-major permuted layout -> each warp streams a fully
// contiguous 64KB region (DRAM page-friendly). 512 thr x grid 128, single wave.
// Warp owns 8 gate-rows (wid + r*2048) = 2 units x 4 batches; h in smem.
// ---------------------------------------------------------------------------
__global__ void __launch_bounds__(512, 1) k_step(int t) {
    extern __shared__ float sh[];        // 64 KB: h[4 batches][4096]
    int tid = threadIdx.x;
    const float* hin = d_H[t & 1];
    float* hout = d_H[(t + 1) & 1];

    {
        const float4* h4 = (const float4*)hin;
        float4* s4 = (float4*)sh;
        #pragma unroll
        for (int i = 0; i < 8; i++)
            s4[tid + i * 512] = h4[tid + i * 512];
    }
    __syncthreads();

    int wid = blockIdx.x * 16 + (tid >> 5);   // 0..2047
    int lane = tid & 31;

    // warp's contiguous W stream: 32 kc x 8 r x 32 lane uint2
    const uint2* Wp = d_Wp + (size_t)wid * 8192;

    u64t acc[8][4];
    #pragma unroll
    for (int r = 0; r < 8; r++)
        #pragma unroll
        for (int b = 0; b < 4; b++) acc[r][b] = 0ull;

    const ulonglong2* shu = (const ulonglong2*)sh;

    uint2 cur[8];
    #pragma unroll
    for (int r = 0; r < 8; r++)
        cur[r] = Wp[r * 32 + lane];

    #pragma unroll 2
    for (int kc = 0; kc < 32; kc++) {
        int g = kc * 32 + lane;
        uint2 nxt[8];
        if (kc < 31) {
            const uint2* Wn = Wp + (kc + 1) * 256;
            #pragma unroll
            for (int r = 0; r < 8; r++)
                nxt[r] = Wn[r * 32 + lane];
        }
        ulonglong2 hA[4];
        #pragma unroll
        for (int b = 0; b < 4; b++)
            hA[b] = shu[b * 1024 + g];
        #pragma unroll
        for (int r = 0; r < 8; r++) {
            u64t w0 = h2f2(cur[r].x), w1 = h2f2(cur[r].y);
            #pragma unroll
            for (int b = 0; b < 4; b++) {
                fma2(acc[r][b], w0, hA[b].x);
                fma2(acc[r][b], w1, hA[b].y);
            }
        }
        #pragma unroll
        for (int r = 0; r < 8; r++) cur[r] = nxt[r];
    }

    float fa[8][4];
    #pragma unroll
    for (int r = 0; r < 8; r++)
        #pragma unroll
        for (int b = 0; b < 4; b++) {
            float2 f = upk(acc[r][b]);
            float v = f.x + f.y;
            #pragma unroll
            for (int o = 16; o; o >>= 1) v += __shfl_xor_sync(0xffffffffu, v, o);
            fa[r][b] = v;
        }

    if (lane == 0) {
        #pragma unroll
        for (int j = 0; j < 2; j++) {
            int u = wid + j * 2048;
            #pragma unroll
            for (int b = 0; b < 4; b++) {
                size_t xb = ((size_t)b * TT + t) * G4;
                float gi = fa[j][b]     + d_XP[xb + u];
                float gf = fa[j + 2][b] + d_XP[xb + u + 4096];
                float gg = fa[j + 4][b] + d_XP[xb + u + 8192];
                float go = fa[j + 6][b] + d_XP[xb + u + 12288];
                float si = 1.f / (1.f + expf(-gi));
                float sf = 1.f / (1.f + expf(-gf));
                float so = 1.f / (1.f + expf(-go));
                float c = sf * d_C[b * LSTM_H + u] + si * tanhf(gg);
                d_C[b * LSTM_H + u] = c;
                hout[b * LSTM_H + u] = so * tanhf(c);
            }
        }
    }
}

// ---------------------------------------------------------------------------
// Final FC
// ---------------------------------------------------------------------------
__global__ void k_fc(const float* __restrict__ fcW, const float* __restrict__ fcb,
                     float* __restrict__ out) {
    int i = threadIdx.x;  // 0..127
    int b = i >> 5, n = i & 31;
    const float* h = &d_H[0][0] + b * LSTM_H + n * 128;  // T=32 -> parity 0
    float s = 0.f;
    #pragma unroll
    for (int l = 0; l < 128; l++) s += h[l] * fcW[l];
    out[i] = s + fcb[0];
}

extern "C" void kernel_launch(void* const* d_in, const int* in_sizes, int n_in,
                              void* d_out, int out_size) {
    const float* x       = (const float*)d_in[0];
    const void*  ei      = d_in[1];
    const float* ln_g    = (const float*)d_in[2];
    const float* ln_b    = (const float*)d_in[3];
    const float* W1      = (const float*)d_in[4];
    const float* b1      = (const float*)d_in[5];
    const float* W2      = (const float*)d_in[6];
    const float* b2      = (const float*)d_in[7];
    const float* Wih     = (const float*)d_in[8];
    const float* bih     = (const float*)d_in[9];
    const float* Whh     = (const float*)d_in[10];
    const float* bhh     = (const float*)d_in[11];
    const float* fcW     = (const float*)d_in[12];
    const float* fcb     = (const float*)d_in[13];

    static int attr_set = 0;
    if (!attr_set) {
        cudaFuncSetAttribute(k_step, cudaFuncAttributeMaxDynamicSharedMemorySize, 65536);
        cudaFuncSetAttribute(k_xproj, cudaFuncAttributeMaxDynamicSharedMemorySize, XSMEM);
        attr_set = 1;
    }

    k_setup<<<1, 256>>>((const long long*)ei, (const int*)ei);
    k_cvt2<<<65536, 256>>>(Whh);
    k_gcn<<<BB * TT, 256>>>(x, ln_g, ln_b, W1, b1, W2, b2);
    k_xproj<<<128, 512, XSMEM>>>(Wih, bih, bhh);
    for (int t = 0; t < TT; t++) k_step<<<128, 512, 65536>>>(t);
    k_fc<<<1, 128>>>(fcW, fcb, (float*)d_out);
}